// round 4
// baseline (speedup 1.0000x reference)
#include <cuda_runtime.h>
#include <cuda_bf16.h>
#include <cstdint>

#define NB   16           // b's per block
#define TPB  256          // 16 threads per b
#define EPS  1e-6f
typedef unsigned long long ull;

// dynamic smem layout (floats):
//   sRp    : [0,            NB*576)        36864 B
//   sgsym  : [NB*576,       +NB*216)       13824 B (duplicated pairs for f32x2)
//   sgt    : [...,          +NB*9)           576 B
//   srot   : [...,          +108)            432 B
#define OFF_RP    0
#define OFF_GSYM  (NB * 576)
#define OFF_GT    (OFF_GSYM + NB * 216)
#define OFF_ROT   (OFF_GT + NB * 9)
#define SMEM_FLOATS (OFF_ROT + 108)
#define SMEM_BYTES  (SMEM_FLOATS * 4)

__device__ float g_partial[4096];
__device__ unsigned int g_count = 0;   // self-resetting via atomicInc wrap

__global__ __launch_bounds__(TPB)
void geo_fused(const float* __restrict__ R_pred,
               const float* __restrict__ R_gt,
               const float* __restrict__ rot,
               float* __restrict__ out,
               int B, int grid, float invB)
{
    extern __shared__ float smem[];
    float* sRp   = smem + OFF_RP;
    float* sgsym = smem + OFF_GSYM;
    float* sgt   = smem + OFF_GT;
    float* srot  = smem + OFF_ROT;

    __shared__ float ssum;
    __shared__ int slast;
    __shared__ float warpsum[TPB / 32];

    const int tid = threadIdx.x;
    const int b0  = blockIdx.x * NB;
    const int nb  = min(NB, B - b0);

    // ---- stage R_pred slice, coalesced float4 (nb*144 float4, MLP=9/thread) ----
    {
        const float4* src = reinterpret_cast<const float4*>(R_pred + (size_t)b0 * 576);
        float4* dst = reinterpret_cast<float4*>(sRp);
        const int n4 = nb * 144;
        #pragma unroll
        for (int i = tid; i < n4; i += TPB) dst[i] = __ldg(src + i);
    }
    if (tid < 108) srot[tid] = __ldg(rot + tid);
    if (tid < nb * 9) sgt[tid] = __ldg(R_gt + (size_t)b0 * 9 + tid);
    if (tid == 0) ssum = 0.0f;
    __syncthreads();

    // ---- Gsym[b,s,i,k] = sum_j rot[s,i,j]*R_gt[b,j,k], stored duplicated (v,v) ----
    for (int i = tid; i < nb * 108; i += TPB) {
        int bl = i / 108;
        int r  = i - bl * 108;
        int s  = r / 9;
        int e  = r - s * 9;
        int ii = e / 3, kk = e - ii * 3;
        const float* ro = srot + s * 9;
        const float* gt = sgt + bl * 9;
        float v = fmaf(ro[ii*3+2], gt[6+kk],
                  fmaf(ro[ii*3+1], gt[3+kk],
                       ro[ii*3+0] * gt[0+kk]));
        float2 d; d.x = v; d.y = v;
        *reinterpret_cast<float2*>(&sgsym[i * 2]) = d;
    }
    __syncthreads();

    // ---- per-thread: 4 candidates of one b ----
    const int bl = tid >> 4;
    const int m  = tid & 15;
    float cmax = -1e30f;

    if (bl < nb) {
        float rp[36];
        const float4* p4 = reinterpret_cast<const float4*>(&sRp[(bl * 64 + m * 4) * 9]);
        #pragma unroll
        for (int k = 0; k < 9; k++) {        // conflict-free LDS.128 phase pattern
            float4 v = p4[k];
            rp[4*k+0] = v.x; rp[4*k+1] = v.y; rp[4*k+2] = v.z; rp[4*k+3] = v.w;
        }

        ull a[9], bq[9];
        #pragma unroll
        for (int e = 0; e < 9; e++) {
            asm("mov.b64 %0, {%1, %2};" : "=l"(a[e])  : "f"(rp[e]),      "f"(rp[9  + e]));
            asm("mov.b64 %0, {%1, %2};" : "=l"(bq[e]) : "f"(rp[18 + e]), "f"(rp[27 + e]));
        }

        const ull* gsp = reinterpret_cast<const ull*>(&sgsym[(bl * 12) * 18]);
        #pragma unroll
        for (int s = 0; s < 12; s++) {
            ull acc0 = 0ull, acc1 = 0ull;
            #pragma unroll
            for (int e = 0; e < 9; e++) {
                ull gs = gsp[s * 9 + e];     // warp-uniform broadcast LDS.64
                asm("fma.rn.f32x2 %0, %1, %2, %3;" : "=l"(acc0) : "l"(a[e]),  "l"(gs), "l"(acc0));
                asm("fma.rn.f32x2 %0, %1, %2, %3;" : "=l"(acc1) : "l"(bq[e]), "l"(gs), "l"(acc1));
            }
            float t0, t1, t2, t3;
            asm("mov.b64 {%0, %1}, %2;" : "=f"(t0), "=f"(t1) : "l"(acc0));
            asm("mov.b64 {%0, %1}, %2;" : "=f"(t2), "=f"(t3) : "l"(acc1));
            cmax = fmaxf(cmax, fmaxf(fmaxf(t0, t1), fmaxf(t2, t3)));
        }
    }

    #pragma unroll
    for (int w = 8; w >= 1; w >>= 1)
        cmax = fmaxf(cmax, __shfl_xor_sync(0xFFFFFFFFu, cmax, w));

    if (m == 0 && bl < nb) {
        float cosv = (cmax - 1.0f) * 0.5f;
        cosv = fminf(fmaxf(cosv, -1.0f + EPS), 1.0f - EPS);
        atomicAdd(&ssum, acosf(cosv));       // 16 shared atomics per block
    }
    __syncthreads();

    // ---- publish partial; last block reduces (counter self-resets by wrap) ----
    if (tid == 0) {
        g_partial[blockIdx.x] = ssum;
        __threadfence();
        unsigned int old = atomicInc(&g_count, (unsigned int)(grid - 1));
        slast = (old == (unsigned int)(grid - 1));
    }
    __syncthreads();

    if (slast) {
        float v = 0.0f;
        for (int i = tid; i < grid; i += TPB) v += __ldcg(&g_partial[i]);
        #pragma unroll
        for (int w = 16; w >= 1; w >>= 1)
            v += __shfl_xor_sync(0xFFFFFFFFu, v, w);
        if ((tid & 31) == 0) warpsum[tid >> 5] = v;
        __syncthreads();
        if (tid < TPB / 32) {
            float w2 = warpsum[tid];
            #pragma unroll
            for (int w = TPB / 64; w >= 1; w >>= 1)
                w2 += __shfl_xor_sync(0xFFu, w2, w);
            if (tid == 0) out[0] = w2 * invB;
        }
    }
}

extern "C" void kernel_launch(void* const* d_in, const int* in_sizes, int n_in,
                              void* d_out, int out_size)
{
    const float* R_pred = (const float*)d_in[0];
    const float* R_gt   = (const float*)d_in[1];
    const float* rot    = (const float*)d_in[2];
    float* out = (float*)d_out;

    const int B = in_sizes[1] / 9;
    const int grid = (B + NB - 1) / NB;

    cudaFuncSetAttribute(geo_fused, cudaFuncAttributeMaxDynamicSharedMemorySize, SMEM_BYTES);
    geo_fused<<<grid, TPB, SMEM_BYTES>>>(R_pred, R_gt, rot, out, B, grid, 1.0f / (float)B);
}

// round 5
// speedup vs baseline: 1.2023x; 1.2023x over previous
#include <cuda_runtime.h>
#include <cuda_bf16.h>
#include <cstdint>

#define NB   8            // b's per block
#define TPB  128          // 16 threads per b
#define EPS  1e-6f
typedef unsigned long long ull;

// dynamic smem layout (floats):
//   sRp   : [0, NB*576)                  18432 B
//   sgsym : [NB*576, +NB*12*20)           7680 B  (pairs duplicated, 80B per (b,s))
//   sgt   : next NB*9                      288 B
//   srot  : next 108                       432 B
#define OFF_RP    0
#define OFF_GSYM  (NB * 576)
#define OFF_GT    (OFF_GSYM + NB * 240)
#define OFF_ROT   (OFF_GT + NB * 9)
#define SMEM_FLOATS (OFF_ROT + 108)
#define SMEM_BYTES  (SMEM_FLOATS * 4)

__device__ float g_partial[8192];
__device__ unsigned int g_count = 0;   // self-resets via atomicInc wrap

__global__ __launch_bounds__(TPB, 8)
void geo_fused(const float* __restrict__ R_pred,
               const float* __restrict__ R_gt,
               const float* __restrict__ rot,
               float* __restrict__ out,
               int B, int grid, float invB)
{
    extern __shared__ float smem[];
    float* sRp   = smem + OFF_RP;
    float* sgsym = smem + OFF_GSYM;
    float* sgt   = smem + OFF_GT;
    float* srot  = smem + OFF_ROT;

    __shared__ float ssum;
    __shared__ int slast;
    __shared__ float warpsum[TPB / 32];

    const int tid = threadIdx.x;
    const int b0  = blockIdx.x * NB;
    const int nb  = min(NB, B - b0);

    // ---- 1) kick off async staging of R_pred slice (9 x 16B per thread) ----
    {
        const float4* src = reinterpret_cast<const float4*>(R_pred + (size_t)b0 * 576);
        const int n4 = nb * 144;           // = 1152 when nb==8 -> exactly 9 iters
        #pragma unroll 9
        for (int i = tid; i < n4; i += TPB) {
            uint32_t daddr = (uint32_t)__cvta_generic_to_shared(
                reinterpret_cast<float4*>(sRp) + i);
            asm volatile("cp.async.cg.shared.global [%0], [%1], 16;"
                         :: "r"(daddr), "l"(src + i) : "memory");
        }
        asm volatile("cp.async.commit_group;" ::: "memory");
    }

    // ---- 2) small tables while the bulk copy flies ----
    if (tid < 108) srot[tid] = __ldg(rot + tid);
    if (tid < nb * 9) sgt[tid] = __ldg(R_gt + (size_t)b0 * 9 + tid);
    if (tid == 0) ssum = 0.0f;
    __syncthreads();

    // ---- 3) Gsym (still overlapped with cp.async):
    //      Gsym[b,s,i,k] = sum_j rot[s,i,j]*R_gt[b,j,k]; store duplicated (v,v),
    //      80B per (b,s) so each s-op is one 16B-aligned run of 5 float4s.
    {
        const int bl = tid >> 4;
        const int m  = tid & 15;
        if (bl < nb) {
            const float* gt = sgt + bl * 9;
            float* gbase = sgsym + bl * 240;
            #pragma unroll
            for (int r = m; r < 108; r += 16) {
                int s  = r / 9;
                int e  = r - s * 9;
                int ii = e / 3, kk = e - ii * 3;
                const float* ro = srot + s * 9;
                float v = fmaf(ro[ii*3+2], gt[6+kk],
                          fmaf(ro[ii*3+1], gt[3+kk],
                               ro[ii*3+0] * gt[0+kk]));
                float2 d; d.x = v; d.y = v;
                *reinterpret_cast<float2*>(gbase + s * 20 + e * 2) = d;
            }
        }
    }
    asm volatile("cp.async.wait_group 0;" ::: "memory");
    __syncthreads();

    // ---- 4) main compute: 4 candidates per thread, f32x2 pairs ----
    const int bl = tid >> 4;
    const int m  = tid & 15;
    float cmax = -1e30f;

    if (bl < nb) {
        float rp[36];
        const float4* p4 = reinterpret_cast<const float4*>(&sRp[(bl * 64 + m * 4) * 9]);
        #pragma unroll
        for (int k = 0; k < 9; k++) {      // conflict-free: 4 phases, banks disjoint
            float4 v = p4[k];
            rp[4*k+0] = v.x; rp[4*k+1] = v.y; rp[4*k+2] = v.z; rp[4*k+3] = v.w;
        }

        ull a[9], bq[9];
        #pragma unroll
        for (int e = 0; e < 9; e++) {
            asm("mov.b64 %0, {%1, %2};" : "=l"(a[e])  : "f"(rp[e]),      "f"(rp[9  + e]));
            asm("mov.b64 %0, {%1, %2};" : "=l"(bq[e]) : "f"(rp[18 + e]), "f"(rp[27 + e]));
        }

        const float* gb = sgsym + bl * 240;
        #pragma unroll
        for (int s = 0; s < 12; s++) {
            // 5 broadcast LDS.128: each yields two duplicated-pair operands
            const ull* gp = reinterpret_cast<const ull*>(gb + s * 20);
            ull g[9];
            #pragma unroll
            for (int h = 0; h < 4; h++) {
                ulonglong2 q = reinterpret_cast<const ulonglong2*>(gp)[h];
                g[2*h] = q.x; g[2*h+1] = q.y;
            }
            g[8] = gp[8];

            ull acc0 = 0ull, acc1 = 0ull;
            #pragma unroll
            for (int e = 0; e < 9; e++) {
                asm("fma.rn.f32x2 %0, %1, %2, %3;" : "=l"(acc0) : "l"(a[e]),  "l"(g[e]), "l"(acc0));
                asm("fma.rn.f32x2 %0, %1, %2, %3;" : "=l"(acc1) : "l"(bq[e]), "l"(g[e]), "l"(acc1));
            }
            float t0, t1, t2, t3;
            asm("mov.b64 {%0, %1}, %2;" : "=f"(t0), "=f"(t1) : "l"(acc0));
            asm("mov.b64 {%0, %1}, %2;" : "=f"(t2), "=f"(t3) : "l"(acc1));
            cmax = fmaxf(cmax, fmaxf(fmaxf(t0, t1), fmaxf(t2, t3)));
        }
    }

    #pragma unroll
    for (int w = 8; w >= 1; w >>= 1)
        cmax = fmaxf(cmax, __shfl_xor_sync(0xFFFFFFFFu, cmax, w));

    if (m == 0 && bl < nb) {
        float cosv = (cmax - 1.0f) * 0.5f;
        cosv = fminf(fmaxf(cosv, -1.0f + EPS), 1.0f - EPS);
        atomicAdd(&ssum, acosf(cosv));     // 8 shared atomics per block
    }
    __syncthreads();

    // ---- 5) publish partial; last block reduces (counter wraps to 0) ----
    if (tid == 0) {
        g_partial[blockIdx.x] = ssum;
        __threadfence();
        unsigned int old = atomicInc(&g_count, (unsigned int)(grid - 1));
        slast = (old == (unsigned int)(grid - 1));
    }
    __syncthreads();

    if (slast) {
        float v = 0.0f;
        for (int i = tid; i < grid; i += TPB) v += __ldcg(&g_partial[i]);
        #pragma unroll
        for (int w = 16; w >= 1; w >>= 1)
            v += __shfl_xor_sync(0xFFFFFFFFu, v, w);
        if ((tid & 31) == 0) warpsum[tid >> 5] = v;
        __syncthreads();
        if (tid < TPB / 32) {
            float w2 = warpsum[tid];
            #pragma unroll
            for (int w = TPB / 64; w >= 1; w >>= 1)
                w2 += __shfl_xor_sync(0xFFu, w2, w);
            if (tid == 0) out[0] = w2 * invB;
        }
    }
}

extern "C" void kernel_launch(void* const* d_in, const int* in_sizes, int n_in,
                              void* d_out, int out_size)
{
    const float* R_pred = (const float*)d_in[0];
    const float* R_gt   = (const float*)d_in[1];
    const float* rot    = (const float*)d_in[2];
    float* out = (float*)d_out;

    const int B = in_sizes[1] / 9;
    const int grid = (B + NB - 1) / NB;

    cudaFuncSetAttribute(geo_fused, cudaFuncAttributeMaxDynamicSharedMemorySize, SMEM_BYTES);
    geo_fused<<<grid, TPB, SMEM_BYTES>>>(R_pred, R_gt, rot, out, B, grid, 1.0f / (float)B);
}

// round 6
// speedup vs baseline: 1.2399x; 1.0313x over previous
#include <cuda_runtime.h>
#include <cuda_bf16.h>
#include <cstdint>

#define NB   16           // b's per block
#define TPB  256          // 16 threads per b
#define EPS  1e-6f
typedef unsigned long long ull;

// dynamic smem layout (floats):
//   sRp  : [0, NB*576)             36864 B  (R_pred slice, candidate-major)
//   gdup : [NB*576, +240)            960 B  (rot duplicated pairs, 80B per s)
//   sgt  : [+240, +NB*9)             576 B  (R_gt slice)
#define OFF_RP    0
#define OFF_GDUP  (NB * 576)
#define OFF_GT    (OFF_GDUP + 240)
#define SMEM_FLOATS (OFF_GT + NB * 9)
#define SMEM_BYTES  (SMEM_FLOATS * 4)

__device__ float g_partial[4096];
__device__ unsigned int g_count = 0;    // self-resets via atomicInc wrap

__global__ __launch_bounds__(TPB)
void geo_fused(const float* __restrict__ R_pred,
               const float* __restrict__ R_gt,
               const float* __restrict__ rot,
               float* __restrict__ out,
               int B, int grid, float invB)
{
    extern __shared__ float smem[];
    float* sRp  = smem + OFF_RP;
    float* gdup = smem + OFF_GDUP;
    float* sgt  = smem + OFF_GT;

    __shared__ float ssum;
    __shared__ int slast;
    __shared__ float warpsum[TPB / 32];

    const int tid = threadIdx.x;
    const int b0  = blockIdx.x * NB;
    const int nb  = min(NB, B - b0);
    const int n4  = nb * 144;

    // ---- 1) async staging of R_pred slice (coalesced, cvta hoisted) ----
    {
        const float4* src = reinterpret_cast<const float4*>(R_pred + (size_t)b0 * 576) + tid;
        uint32_t daddr = (uint32_t)__cvta_generic_to_shared(sRp) + tid * 16u;
        #pragma unroll
        for (int j = 0; j < 9; j++) {
            if (tid + j * TPB < n4)
                asm volatile("cp.async.cg.shared.global [%0], [%1], 16;"
                             :: "r"(daddr + j * (TPB * 16u)), "l"(src + j * TPB) : "memory");
        }
        asm volatile("cp.async.commit_group;" ::: "memory");
    }

    // ---- 2) small tables while the bulk copy flies ----
    if (tid < 108) {
        int s = tid / 9, e = tid - s * 9;          // one-time, off hot path
        float v = __ldg(rot + tid);
        gdup[s * 20 + e * 2]     = v;
        gdup[s * 20 + e * 2 + 1] = v;
    }
    if (tid < nb * 9) sgt[tid] = __ldg(R_gt + (size_t)b0 * 9 + tid);
    if (tid == 0) ssum = 0.0f;

    asm volatile("cp.async.wait_group 0;" ::: "memory");
    __syncthreads();

    // ---- 3) main compute: 4 candidates per thread ----
    const int bl = tid >> 4;
    const int m  = tid & 15;
    float cmax = -1e30f;

    if (bl < nb) {
        // R_gt for this b (broadcast LDS)
        float g[9];
        const float* gt = sgt + bl * 9;
        #pragma unroll
        for (int k = 0; k < 9; k++) g[k] = gt[k];

        // 4 candidates = 9 conflict-free LDS.128
        float rp[36];
        const float4* p4 = reinterpret_cast<const float4*>(&sRp[(bl * 64 + m * 4) * 9]);
        #pragma unroll
        for (int k = 0; k < 9; k++) {
            float4 v = p4[k];
            rp[4*k+0] = v.x; rp[4*k+1] = v.y; rp[4*k+2] = v.z; rp[4*k+3] = v.w;
        }

        // M[c][i*3+k] = sum_j rp[c,i,j] * g[k*3+j]; pack candidate pairs
        ull a[9], bq[9];
        #pragma unroll
        for (int e = 0; e < 9; e++) {
            const int i3 = (e / 3) * 3, k3 = (e % 3) * 3;
            float m0 = fmaf(rp[ 0+i3+2], g[k3+2], fmaf(rp[ 0+i3+1], g[k3+1], rp[ 0+i3] * g[k3]));
            float m1 = fmaf(rp[ 9+i3+2], g[k3+2], fmaf(rp[ 9+i3+1], g[k3+1], rp[ 9+i3] * g[k3]));
            float m2 = fmaf(rp[18+i3+2], g[k3+2], fmaf(rp[18+i3+1], g[k3+1], rp[18+i3] * g[k3]));
            float m3 = fmaf(rp[27+i3+2], g[k3+2], fmaf(rp[27+i3+1], g[k3+1], rp[27+i3] * g[k3]));
            asm("mov.b64 %0, {%1, %2};" : "=l"(a[e])  : "f"(m0), "f"(m1));
            asm("mov.b64 %0, {%1, %2};" : "=l"(bq[e]) : "f"(m2), "f"(m3));
        }

        // s-loop: tr[c,s] = <rot[s], M[c]> via duplicated-pair f32x2
        #pragma unroll
        for (int s = 0; s < 12; s++) {
            const ull* gp = reinterpret_cast<const ull*>(gdup + s * 20);
            ull gs[9];
            #pragma unroll
            for (int h = 0; h < 4; h++) {           // broadcast LDS.128
                ulonglong2 q = reinterpret_cast<const ulonglong2*>(gp)[h];
                gs[2*h] = q.x; gs[2*h+1] = q.y;
            }
            gs[8] = gp[8];

            ull acc0 = 0ull, acc1 = 0ull;
            #pragma unroll
            for (int e = 0; e < 9; e++) {
                asm("fma.rn.f32x2 %0, %1, %2, %3;" : "=l"(acc0) : "l"(a[e]),  "l"(gs[e]), "l"(acc0));
                asm("fma.rn.f32x2 %0, %1, %2, %3;" : "=l"(acc1) : "l"(bq[e]), "l"(gs[e]), "l"(acc1));
            }
            float2 f0 = *reinterpret_cast<float2*>(&acc0);   // register aliasing, no movs
            float2 f1 = *reinterpret_cast<float2*>(&acc1);
            cmax = fmaxf(cmax, fmaxf(fmaxf(f0.x, f0.y), fmaxf(f1.x, f1.y)));
        }
    }

    // max over the 16 lanes sharing this b
    #pragma unroll
    for (int w = 8; w >= 1; w >>= 1)
        cmax = fmaxf(cmax, __shfl_xor_sync(0xFFFFFFFFu, cmax, w));

    if (m == 0 && bl < nb) {
        float cosv = (cmax - 1.0f) * 0.5f;
        cosv = fminf(fmaxf(cosv, -1.0f + EPS), 1.0f - EPS);
        atomicAdd(&ssum, acosf(cosv));
    }
    __syncthreads();

    // ---- 4) publish partial; last block reduces (counter wraps to 0) ----
    if (tid == 0) {
        g_partial[blockIdx.x] = ssum;
        __threadfence();
        unsigned int old = atomicInc(&g_count, (unsigned int)(grid - 1));
        slast = (old == (unsigned int)(grid - 1));
    }
    __syncthreads();

    if (slast) {
        float v = 0.0f;
        for (int i = tid; i < grid; i += TPB) v += __ldcg(&g_partial[i]);
        #pragma unroll
        for (int w = 16; w >= 1; w >>= 1)
            v += __shfl_xor_sync(0xFFFFFFFFu, v, w);
        if ((tid & 31) == 0) warpsum[tid >> 5] = v;
        __syncthreads();
        if (tid < TPB / 32) {
            float w2 = warpsum[tid];
            #pragma unroll
            for (int w = TPB / 64; w >= 1; w >>= 1)
                w2 += __shfl_xor_sync(0xFFu, w2, w);
            if (tid == 0) out[0] = w2 * invB;
        }
    }
}

extern "C" void kernel_launch(void* const* d_in, const int* in_sizes, int n_in,
                              void* d_out, int out_size)
{
    const float* R_pred = (const float*)d_in[0];
    const float* R_gt   = (const float*)d_in[1];
    const float* rot    = (const float*)d_in[2];
    float* out = (float*)d_out;

    const int B = in_sizes[1] / 9;
    const int grid = (B + NB - 1) / NB;

    cudaFuncSetAttribute(geo_fused, cudaFuncAttributeMaxDynamicSharedMemorySize, SMEM_BYTES);
    geo_fused<<<grid, TPB, SMEM_BYTES>>>(R_pred, R_gt, rot, out, B, grid, 1.0f / (float)B);
}